// round 1
// baseline (speedup 1.0000x reference)
#include <cuda_runtime.h>
#include <cstdint>
#include <cstddef>

// Problem constants
#define DD 88     // input dim
#define HH 256    // hidden dim
#define LL 128    // latent dim
#define BB 128    // batch
#define TT 1024   // seq len
#define KIN (DD + HH)   // 344
#define NCTA 128
#define NTH 256

// SMEM layout (float offsets)
#define WE_OFF 0
#define WD_OFF (8 * KIN)                    // 2752
#define WOUT_OFF (2 * 8 * KIN)              // 5504
#define WDEC0_OFF (WOUT_OFF + HH * DD)      // 28032
#define BE_OFF (WDEC0_OFF + 2 * LL)         // 28288
#define BD_OFF (BE_OFF + 8)                 // 28296
#define BOUT_OFF (BD_OFF + 8)               // 28304
#define BDEC0_OFF (BOUT_OFF + DD)           // 28392
#define RED_OFF (BDEC0_OFF + 8)             // 28400 (padded)
#define SMEM_FLOATS (RED_OFF + 8 * 128)     // 29424
#define SMEM_BYTES (SMEM_FLOATS * 4)        // 117696

static_assert(SMEM_BYTES < 227 * 1024, "smem too big");

// Persistent scratch (device globals; no runtime allocation)
__device__ float g_hT[2][HH * BB];       // hidden state, transposed [H][B], double-buffered
__device__ float g_predT[DD * BB];       // decoder feedback input, transposed [D][B]
__device__ float g_zT[LL * BB];          // latent, transposed [L][B]
__device__ float g_xT[TT * DD * BB];     // x transposed [T][D][B] (~46 MB)
__device__ unsigned long long g_bar;     // grid barrier counter

// ---------------------------------------------------------------------------
// Init kernel: transpose x, zero h0/pred0, reset barrier counter. Runs every
// kernel_launch so replays are deterministic.
// ---------------------------------------------------------------------------
__global__ void lstm_init_kernel(const float* __restrict__ x) {
    const int t = blockIdx.x;
    const int tid = threadIdx.x;
    if (t < TT) {
        const int b = tid;  // 128 threads
        #pragma unroll 8
        for (int d = 0; d < DD; d++) {
            g_xT[(t * DD + d) * BB + b] = x[((size_t)b * TT + t) * DD + d];
        }
    } else {
        if (tid == 0) g_bar = 0ULL;
        for (int i = tid; i < HH * BB; i += 128) g_hT[0][i] = 0.0f;
        for (int i = tid; i < DD * BB; i += 128) g_predT[i] = 0.0f;
    }
}

__device__ __forceinline__ float sigmoidf_(float v) { return 1.0f / (1.0f + expf(-v)); }

#define GATE_FMA(JIDX, VX, VY) do {                            \
    float wi_ = w[0 * KIN + (JIDX)], wf_ = w[1 * KIN + (JIDX)];\
    float wg_ = w[2 * KIN + (JIDX)], wo_ = w[3 * KIN + (JIDX)];\
    ai0 += wi_ * (VX); ai1 += wi_ * (VY);                      \
    af0 += wf_ * (VX); af1 += wf_ * (VY);                      \
    ag0 += wg_ * (VX); ag1 += wg_ * (VY);                      \
    ao0 += wo_ * (VX); ao1 += wo_ * (VY); } while (0)

// ---------------------------------------------------------------------------
// Main persistent kernel: whole encoder + latent + decoder in one launch.
// 128 CTAs x 256 threads. CTA n owns hidden units {2n, 2n+1} and batch row n
// (for the decoder output projection).
// Thread mapping in gate phases: p = tid&63 (batch pair 2p,2p+1),
// ku = (tid>>6)&1 (which of the 2 hidden units), kh = tid>>7 (K-range half).
// ---------------------------------------------------------------------------
__global__ void __launch_bounds__(NTH, 1) lstm_main_kernel(
    const float* __restrict__ Wih_e, const float* __restrict__ Whh_e,
    const float* __restrict__ bih_e, const float* __restrict__ bhh_e,
    const float* __restrict__ Wih_d, const float* __restrict__ Whh_d,
    const float* __restrict__ bih_d, const float* __restrict__ bhh_d,
    const float* __restrict__ W_lat, const float* __restrict__ b_lat,
    const float* __restrict__ W_decinit, const float* __restrict__ b_decinit,
    const float* __restrict__ W_out, const float* __restrict__ b_out,
    float* __restrict__ out)
{
    extern __shared__ float sm[];
    const int n = blockIdx.x;
    const int tid = threadIdx.x;
    const int p = tid & 63;
    const int ku = (tid >> 6) & 1;
    const int kh = tid >> 7;
    const int b0 = 2 * p;
    const int khid = 2 * n + ku;   // hidden index served by this thread's gates

    // ---- stage weights into SMEM ----
    // Gate rows r = rku*4 + rg  (rku in {0,1} local hidden, rg in {i,f,g,o}),
    // each row = [Wih row (88) | Whh row (256)].
    for (int idx = tid; idx < 8 * KIN; idx += NTH) {
        int r = idx / KIN, j = idx - r * KIN;
        int rg = r & 3, rku = r >> 2;
        int grow = rg * HH + 2 * n + rku;
        sm[WE_OFF + idx] = (j < DD) ? Wih_e[grow * DD + j] : Whh_e[grow * HH + (j - DD)];
        sm[WD_OFF + idx] = (j < DD) ? Wih_d[grow * DD + j] : Whh_d[grow * HH + (j - DD)];
    }
    // W_out transposed: sm[WOUT_OFF + kk*DD + d] = W_out[d][kk]
    for (int idx = tid; idx < DD * HH; idx += NTH) {
        int d = idx / HH, kk = idx - d * HH;
        sm[WOUT_OFF + kk * DD + d] = W_out[idx];
    }
    for (int idx = tid; idx < 2 * LL; idx += NTH) {
        int rku = idx >> 7, l = idx & (LL - 1);
        sm[WDEC0_OFF + idx] = W_decinit[(2 * n + rku) * LL + l];
    }
    if (tid < 8) {
        int rg = tid & 3, rku = tid >> 2;
        int grow = rg * HH + 2 * n + rku;
        sm[BE_OFF + tid] = bih_e[grow] + bhh_e[grow];
        sm[BD_OFF + tid] = bih_d[grow] + bhh_d[grow];
    }
    if (tid < DD) sm[BOUT_OFF + tid] = b_out[tid];
    if (tid < 2)  sm[BDEC0_OFF + tid] = b_decinit[2 * n + tid];
    __syncthreads();

    unsigned long long barE = 0;
    int cur = 0;
    float c0 = 0.0f, c1 = 0.0f;   // cell state for (b0,khid), (b0+1,khid) — kh==0 threads

    // Grid barrier: monotonic counter. Release fence before arrive; acquire
    // fence after poll (sm_103a: gpu-scope fence emits CCTL.IVALL -> L1 is
    // invalidated, so cross-SM hT/predT reads are coherent).
    auto gbar = [&]() {
        __syncthreads();
        barE++;
        if (tid == 0) {
            __threadfence();
            atomicAdd(&g_bar, 1ULL);
            const unsigned long long tgt = barE * (unsigned long long)NCTA;
            while (*((volatile unsigned long long*)&g_bar) < tgt) __nanosleep(40);
            __threadfence();
        }
        __syncthreads();
    };

    // One LSTM gate step: gates = inp @ Wih^T + h @ Whh^T + b for this CTA's
    // 8 gate rows, then cell update, write new h slice to g_hT[cur^1].
    auto gate_step = [&](const float* __restrict__ inp, const int wOff, const int bOff) {
        const float* __restrict__ hp = g_hT[cur];
        const float* __restrict__ w = &sm[wOff + (ku * 4) * KIN];
        float ai0, ai1, af0, af1, ag0, ag1, ao0, ao1;
        if (kh == 0) {
            ai0 = ai1 = sm[bOff + ku * 4 + 0];
            af0 = af1 = sm[bOff + ku * 4 + 1];
            ag0 = ag1 = sm[bOff + ku * 4 + 2];
            ao0 = ao1 = sm[bOff + ku * 4 + 3];
            #pragma unroll 4
            for (int j = 0; j < DD; j++) {
                float2 v = *reinterpret_cast<const float2*>(&inp[j * BB + b0]);
                GATE_FMA(j, v.x, v.y);
            }
            #pragma unroll 4
            for (int kk = 0; kk < 128; kk++) {
                float2 v = *reinterpret_cast<const float2*>(&hp[kk * BB + b0]);
                GATE_FMA(DD + kk, v.x, v.y);
            }
        } else {
            ai0 = ai1 = af0 = af1 = ag0 = ag1 = ao0 = ao1 = 0.0f;
            #pragma unroll 4
            for (int kk = 128; kk < 256; kk++) {
                float2 v = *reinterpret_cast<const float2*>(&hp[kk * BB + b0]);
                GATE_FMA(DD + kk, v.x, v.y);
            }
        }
        // cross-half reduction via SMEM (SoA layout: conflict-free)
        if (kh == 1) {
            float* rp = &sm[RED_OFF];
            const int q = tid & 127;
            rp[0 * 128 + q] = ai0; rp[1 * 128 + q] = ai1;
            rp[2 * 128 + q] = af0; rp[3 * 128 + q] = af1;
            rp[4 * 128 + q] = ag0; rp[5 * 128 + q] = ag1;
            rp[6 * 128 + q] = ao0; rp[7 * 128 + q] = ao1;
        }
        __syncthreads();
        if (kh == 0) {
            const float* rp = &sm[RED_OFF];
            ai0 += rp[0 * 128 + tid]; ai1 += rp[1 * 128 + tid];
            af0 += rp[2 * 128 + tid]; af1 += rp[3 * 128 + tid];
            ag0 += rp[4 * 128 + tid]; ag1 += rp[5 * 128 + tid];
            ao0 += rp[6 * 128 + tid]; ao1 += rp[7 * 128 + tid];
            float i0 = sigmoidf_(ai0), i1 = sigmoidf_(ai1);
            float f0 = sigmoidf_(af0), f1 = sigmoidf_(af1);
            float gg0 = tanhf(ag0),    gg1 = tanhf(ag1);
            float o0 = sigmoidf_(ao0), o1 = sigmoidf_(ao1);
            c0 = f0 * c0 + i0 * gg0;
            c1 = f1 * c1 + i1 * gg1;
            float2 hv;
            hv.x = o0 * tanhf(c0);
            hv.y = o1 * tanhf(c1);
            *reinterpret_cast<float2*>(&g_hT[cur ^ 1][khid * BB + b0]) = hv;
        }
    };

    // =============== encoder ===============
    #pragma unroll 1
    for (int t = 0; t < TT; t++) {
        gate_step(&g_xT[t * DD * BB], WE_OFF, BE_OFF);
        gbar();
        cur ^= 1;
    }

    // =============== latent: z = h_n @ W_lat^T + b_lat ===============
    // CTA n computes latent dim l = n for all batches.
    if (tid < BB) {
        const float* __restrict__ hp = g_hT[cur];
        const float* __restrict__ wl = &W_lat[n * HH];
        float a0 = 0.f, a1 = 0.f, a2 = 0.f, a3 = 0.f;
        #pragma unroll 4
        for (int kk = 0; kk < HH; kk += 4) {
            a0 += hp[(kk + 0) * BB + tid] * wl[kk + 0];
            a1 += hp[(kk + 1) * BB + tid] * wl[kk + 1];
            a2 += hp[(kk + 2) * BB + tid] * wl[kk + 2];
            a3 += hp[(kk + 3) * BB + tid] * wl[kk + 3];
        }
        float z = a0 + a1 + a2 + a3 + b_lat[n];
        g_zT[n * BB + tid] = z;
        out[(size_t)BB * TT * DD + (size_t)tid * LL + n] = z;  // z[b][l]
    }
    gbar();

    // =============== decoder init: h_dec0 = z @ W_decinit^T + b ===============
    if (tid < BB) {
        #pragma unroll
        for (int ku2 = 0; ku2 < 2; ku2++) {
            const float* __restrict__ wv = &sm[WDEC0_OFF + ku2 * LL];
            float a0 = 0.f, a1 = 0.f, a2 = 0.f, a3 = 0.f;
            #pragma unroll 4
            for (int l = 0; l < LL; l += 4) {
                a0 += g_zT[(l + 0) * BB + tid] * wv[l + 0];
                a1 += g_zT[(l + 1) * BB + tid] * wv[l + 1];
                a2 += g_zT[(l + 2) * BB + tid] * wv[l + 2];
                a3 += g_zT[(l + 3) * BB + tid] * wv[l + 3];
            }
            g_hT[cur ^ 1][(2 * n + ku2) * BB + tid] = a0 + a1 + a2 + a3 + sm[BDEC0_OFF + ku2];
        }
    }
    gbar();
    cur ^= 1;
    c0 = 0.0f;
    c1 = 0.0f;

    // =============== decoder (autoregressive) ===============
    #pragma unroll 1
    for (int t = 0; t < TT; t++) {
        gate_step(g_predT, WD_OFF, BD_OFF);     // inp = pred of previous step
        gbar();
        cur ^= 1;
        // pred_t = sigmoid(h_t @ W_out^T + b_out); CTA n handles batch row n.
        {
            const float* __restrict__ hp = g_hT[cur];
            const int d = tid & 127;
            const int kb = kh * 128;
            float a0 = 0.f, a1 = 0.f, a2 = 0.f, a3 = 0.f;
            if (d < DD) {
                #pragma unroll 4
                for (int kk = 0; kk < 128; kk += 4) {
                    float h0v = hp[(kb + kk + 0) * BB + n];
                    float h1v = hp[(kb + kk + 1) * BB + n];
                    float h2v = hp[(kb + kk + 2) * BB + n];
                    float h3v = hp[(kb + kk + 3) * BB + n];
                    a0 += h0v * sm[WOUT_OFF + (kb + kk + 0) * DD + d];
                    a1 += h1v * sm[WOUT_OFF + (kb + kk + 1) * DD + d];
                    a2 += h2v * sm[WOUT_OFF + (kb + kk + 2) * DD + d];
                    a3 += h3v * sm[WOUT_OFF + (kb + kk + 3) * DD + d];
                }
            }
            if (kh == 1) sm[RED_OFF + d] = a0 + a1 + a2 + a3;
            __syncthreads();
            if (kh == 0 && d < DD) {
                float v = a0 + a1 + a2 + a3 + sm[RED_OFF + d] + sm[BOUT_OFF + d];
                float pr = sigmoidf_(v);
                g_predT[d * BB + n] = pr;                       // feedback input
                out[((size_t)n * TT + t) * DD + d] = pr;        // outputs[b][t][d]
            }
        }
        gbar();
    }
}

// ---------------------------------------------------------------------------
extern "C" void kernel_launch(void* const* d_in, const int* in_sizes, int n_in,
                              void* d_out, int out_size) {
    const float* x         = (const float*)d_in[0];
    const float* Wih_e     = (const float*)d_in[1];
    const float* Whh_e     = (const float*)d_in[2];
    const float* bih_e     = (const float*)d_in[3];
    const float* bhh_e     = (const float*)d_in[4];
    const float* Wih_d     = (const float*)d_in[5];
    const float* Whh_d     = (const float*)d_in[6];
    const float* bih_d     = (const float*)d_in[7];
    const float* bhh_d     = (const float*)d_in[8];
    const float* W_lat     = (const float*)d_in[9];
    const float* b_lat     = (const float*)d_in[10];
    const float* W_decinit = (const float*)d_in[11];
    const float* b_decinit = (const float*)d_in[12];
    const float* W_out     = (const float*)d_in[13];
    const float* b_out     = (const float*)d_in[14];
    float* out = (float*)d_out;

    // Opt in to >48KB dynamic SMEM (idempotent; not a stream op, capture-safe)
    cudaFuncSetAttribute(lstm_main_kernel,
                         cudaFuncAttributeMaxDynamicSharedMemorySize, SMEM_BYTES);

    lstm_init_kernel<<<TT + 1, 128>>>(x);
    lstm_main_kernel<<<NCTA, NTH, SMEM_BYTES>>>(
        Wih_e, Whh_e, bih_e, bhh_e,
        Wih_d, Whh_d, bih_d, bhh_d,
        W_lat, b_lat, W_decinit, b_decinit, W_out, b_out, out);
}

// round 2
// speedup vs baseline: 2.0935x; 2.0935x over previous
#include <cuda_runtime.h>
#include <cstdint>
#include <cstddef>

typedef unsigned long long ull;

// Problem constants
#define DD 88
#define HH 256
#define LL 128
#define BB 128
#define TT 1024
#define KIN 344            // DD + HH
#define CSZ 8              // cluster size (CTAs)
#define NCLUST 16
#define NCTA 128
#define NTH 256
#define ZOFF ((size_t)BB * TT * DD)   // offset of z in out

// SMEM layout (float offsets)
#define WG_OFF    0                      // [32 hid][345 j pad][4 gates] = 44160
#define IN_OFF    44160                  // inbuf[2][344][8] = 5504
#define RED_OFF   49664                  // [4][128] ull = 1024 floats
#define HLOC_OFF  50688                  // [32][8] = 256
#define PPART_OFF 50944                  // [8 src][88] = 704
#define WOUTS_OFF 51648                  // [32 k][88 d] = 2816
#define ZBUF_OFF  54464                  // [128 l][8 b] = 1024
#define BGE_OFF   55488                  // [32][4] = 128
#define BGD_OFF   55616                  // 128
#define BOUTS_OFF 55744                  // 88 (pad 96)
#define SMEM_FLOATS 55840
#define SMEM_BYTES (SMEM_FLOATS * 4)     // 223360 B

static_assert(SMEM_BYTES <= 232448, "smem too big");

// x retransposed: g_x2[t][cluster][d][8] (contiguous 704 floats per (t,cluster))
__device__ float g_x2[(size_t)TT * NCLUST * DD * 8];

// ---------------------------------------------------------------------------
__global__ void lstm_init_kernel(const float* __restrict__ x) {
    const int t = blockIdx.x;
    const int b = threadIdx.x;
    #pragma unroll 8
    for (int d = 0; d < DD; d++) {
        g_x2[((size_t)t * NCLUST + (b >> 3)) * (DD * 8) + d * 8 + (b & 7)] =
            x[((size_t)b * TT + t) * DD + d];
    }
}

// ---------------------------------------------------------------------------
__device__ __forceinline__ float sigf(float v) { return 1.0f / (1.0f + expf(-v)); }

__device__ __forceinline__ ull pk2(float x, float y) {
    ull r; asm("mov.b64 %0, {%1, %2};" : "=l"(r) : "f"(x), "f"(y)); return r;
}
__device__ __forceinline__ float2 upk2(ull v) {
    float2 r; asm("mov.b64 {%0, %1}, %2;" : "=f"(r.x), "=f"(r.y) : "l"(v)); return r;
}
#define FMA2(acc, a, b) asm("fma.rn.f32x2 %0, %1, %2, %0;" : "+l"(acc) : "l"(a), "l"(b))

#define CLUSTER_SYNC() do { \
    asm volatile("barrier.cluster.arrive.aligned;" ::: "memory"); \
    asm volatile("barrier.cluster.wait.aligned;" ::: "memory");   \
} while (0)

__device__ __forceinline__ void st_remote64(const void* lptr, int rank, ull v) {
    uint32_t la = (uint32_t)__cvta_generic_to_shared(lptr), ra;
    asm("mapa.shared::cluster.u32 %0, %1, %2;" : "=r"(ra) : "r"(la), "r"(rank));
    asm volatile("st.shared::cluster.b64 [%0], %1;" :: "r"(ra), "l"(v) : "memory");
}
__device__ __forceinline__ void st_remote32(const void* lptr, int rank, float v) {
    uint32_t la = (uint32_t)__cvta_generic_to_shared(lptr), ra;
    asm("mapa.shared::cluster.u32 %0, %1, %2;" : "=r"(ra) : "r"(la), "r"(rank));
    asm volatile("st.shared::cluster.b32 [%0], %1;" :: "r"(ra), "r"(__float_as_uint(v)) : "memory");
}

// Stage this CTA's 128 gate rows into wg: layout [hid][j pad345][gate(i,f,g,o)]
__device__ __forceinline__ void stage_w(float* wg, const float* __restrict__ Wih,
                                        const float* __restrict__ Whh,
                                        int RANK, int tid) {
    for (int idx = tid; idx < 32 * KIN; idx += NTH) {
        int h = idx / KIN, j = idx - h * KIN;
        int rowbase = RANK * 32 + h;
        float* d = wg + h * 1380 + j * 4;
        if (j < DD) {
            #pragma unroll
            for (int g = 0; g < 4; g++) d[g] = Wih[((size_t)(g * HH + rowbase)) * DD + j];
        } else {
            int jj = j - DD;
            #pragma unroll
            for (int g = 0; g < 4; g++) d[g] = Whh[((size_t)(g * HH + rowbase)) * HH + jj];
        }
    }
}

// ---------------------------------------------------------------------------
// 16 clusters x 8 CTAs x 256 threads. Cluster = 8 batch columns.
// CTA rank r owns hidden units [r*32, (r+1)*32) and (decoder) batch r.
// Thread map in gates: p=tid&3 (batch pair 2p), hid=(tid>>2)&31, kh=tid>>7.
// ---------------------------------------------------------------------------
__global__ void __launch_bounds__(NTH, 1) __cluster_dims__(CSZ, 1, 1)
lstm_cluster_kernel(
    const float* __restrict__ Wih_e, const float* __restrict__ Whh_e,
    const float* __restrict__ bih_e, const float* __restrict__ bhh_e,
    const float* __restrict__ Wih_d, const float* __restrict__ Whh_d,
    const float* __restrict__ bih_d, const float* __restrict__ bhh_d,
    const float* __restrict__ W_lat, const float* __restrict__ b_lat,
    const float* __restrict__ W_decinit, const float* __restrict__ b_decinit,
    const float* __restrict__ W_out, const float* __restrict__ b_out,
    float* __restrict__ out)
{
    extern __shared__ float sm[];
    float* wg     = sm + WG_OFF;
    float* inb    = sm + IN_OFF;
    ull*   red64  = (ull*)(sm + RED_OFF);
    float* hloc   = sm + HLOC_OFF;
    float* ppart  = sm + PPART_OFF;
    float* wout_s = sm + WOUTS_OFF;
    float* zbuf   = sm + ZBUF_OFF;
    float* bge    = sm + BGE_OFF;
    float* bgd    = sm + BGD_OFF;
    float* bout_s = sm + BOUTS_OFF;

    const int tid = threadIdx.x;
    const int RANK = blockIdx.x & (CSZ - 1);
    const int CLUST = blockIdx.x >> 3;
    const int p = tid & 3;
    const int hid = (tid >> 2) & 31;
    const int kh = tid >> 7;
    const int q = tid & 127;
    const int b0 = 2 * p;
    const int ghid = RANK * 32 + hid;

    // ---- one-time staging ----
    stage_w(wg, Wih_e, Whh_e, RANK, tid);
    if (tid < 128) {
        int h2 = tid >> 2, g = tid & 3;
        int row = g * HH + RANK * 32 + h2;
        bge[tid] = bih_e[row] + bhh_e[row];
        bgd[tid] = bih_d[row] + bhh_d[row];
    }
    for (int idx = tid; idx < 32 * DD; idx += NTH) {   // wout_s[k][d]
        int d8 = idx >> 5, k = idx & 31;
        wout_s[k * DD + d8] = W_out[(size_t)d8 * HH + RANK * 32 + k];
    }
    if (tid < DD) bout_s[tid] = b_out[tid];
    // inbuf[0]: h rows zero, x rows = x[0]
    for (int idx = tid; idx < HH * 8; idx += NTH) inb[DD * 8 + idx] = 0.0f;
    if (tid < 176) {
        *(float4*)(inb + tid * 4) =
            *(const float4*)(g_x2 + ((size_t)0 * NCLUST + CLUST) * (DD * 8) + tid * 4);
    }
    CLUSTER_SYNC();

    int cur = 0;
    float c0 = 0.0f, c1 = 0.0f;   // cell state (kh==0 threads): (ghid, b0), (ghid, b0+1)
    const int j0 = kh * 172;

    // ---- gate step body (macro so it inlines identically for enc/dec) ----
    ull a0, a1, a2, a3;
    float h0v, h1v;
#define GATE_STEP(BIAS)                                                        \
    do {                                                                       \
        const float* wrow = wg + hid * 1380;                                   \
        const float* ib = inb + cur * (KIN * 8);                               \
        if (kh == 0) {                                                         \
            float2 bif = *(const float2*)(BIAS + hid * 4);                     \
            float2 bgo = *(const float2*)(BIAS + hid * 4 + 2);                 \
            a0 = a2 = pk2(bif.x, bif.y);                                       \
            a1 = a3 = pk2(bgo.x, bgo.y);                                       \
        } else { a0 = a1 = a2 = a3 = 0ULL; }                                   \
        _Pragma("unroll 4")                                                    \
        for (int j = j0; j < j0 + 172; j++) {                                  \
            const ulonglong2 w = *(const ulonglong2*)(wrow + j * 4);           \
            const float2 v = *(const float2*)(ib + j * 8 + b0);                \
            ull vx = pk2(v.x, v.x), vy = pk2(v.y, v.y);                        \
            FMA2(a0, w.x, vx); FMA2(a1, w.y, vx);                              \
            FMA2(a2, w.x, vy); FMA2(a3, w.y, vy);                              \
        }                                                                      \
        if (kh == 1) {                                                         \
            red64[q] = a0; red64[128 + q] = a1;                                \
            red64[256 + q] = a2; red64[384 + q] = a3;                          \
        }                                                                      \
        __syncthreads();                                                       \
        if (kh == 0) {                                                         \
            float2 s0 = upk2(a0), s1 = upk2(a1), s2 = upk2(a2), s3 = upk2(a3); \
            float2 r0 = upk2(red64[q]),       r1 = upk2(red64[128 + q]);       \
            float2 r2 = upk2(red64[256 + q]), r3 = upk2(red64[384 + q]);       \
            float i0 = sigf(s0.x + r0.x), f0 = sigf(s0.y + r0.y);              \
            float g0 = tanhf(s1.x + r1.x), o0 = sigf(s1.y + r1.y);             \
            float i1 = sigf(s2.x + r2.x), f1 = sigf(s2.y + r2.y);              \
            float g1 = tanhf(s3.x + r3.x), o1 = sigf(s3.y + r3.y);             \
            c0 = f0 * c0 + i0 * g0;  h0v = o0 * tanhf(c0);                     \
            c1 = f1 * c1 + i1 * g1;  h1v = o1 * tanhf(c1);                     \
            ull hv = pk2(h0v, h1v);                                            \
            const float* dst = inb + (cur ^ 1) * (KIN * 8) + (DD + ghid) * 8 + b0; \
            _Pragma("unroll")                                                  \
            for (int r8 = 0; r8 < CSZ; r8++) st_remote64(dst, r8, hv);         \
        }                                                                      \
    } while (0)

    // =============== encoder ===============
    #pragma unroll 1
    for (int t = 0; t < TT; t++) {
        float4 xreg;
        const bool havex = (t + 1 < TT) && (tid < 176);
        if (havex)
            xreg = *(const float4*)(g_x2 + ((size_t)(t + 1) * NCLUST + CLUST) * (DD * 8) + tid * 4);
        GATE_STEP(bge);
        if (havex) *(float4*)(inb + (cur ^ 1) * (KIN * 8) + tid * 4) = xreg;
        CLUSTER_SYNC();
        cur ^= 1;
    }

    // =============== latent z ===============
    if (tid < 128) {
        const int li = tid >> 3, b = tid & 7;
        const int l = RANK * 16 + li;
        const float* wl = W_lat + (size_t)l * HH;
        const float* hb = inb + cur * (KIN * 8) + DD * 8 + b;
        float acc = 0.0f;
        #pragma unroll 8
        for (int k = 0; k < HH; k++) acc += wl[k] * hb[k * 8];
        float z = acc + b_lat[l];
        out[ZOFF + ((size_t)(CLUST * 8 + b)) * LL + l] = z;
        const float* dstz = zbuf + l * 8 + b;
        #pragma unroll
        for (int r8 = 0; r8 < CSZ; r8++) st_remote32(dstz, r8, z);
    }
    CLUSTER_SYNC();

    // restage decoder weights (no one reads wg now)
    stage_w(wg, Wih_d, Whh_d, RANK, tid);
    // zero x rows (pred0 = 0) in inbuf[cur^1]
    if (tid < 176) {
        *(float4*)(inb + (cur ^ 1) * (KIN * 8) + tid * 4) = make_float4(0.f, 0.f, 0.f, 0.f);
    }
    // decoder init: h0 = z @ W_decinit^T + b
    if (tid < 128) {
        const int pd = tid & 3, hd = tid >> 2;
        const int gh = RANK * 32 + hd;
        const float* wd = W_decinit + (size_t)gh * LL;
        float acc0 = b_decinit[gh], acc1 = acc0;
        #pragma unroll 8
        for (int k = 0; k < LL; k++) {
            float2 v = *(const float2*)(zbuf + k * 8 + 2 * pd);
            acc0 += wd[k] * v.x;
            acc1 += wd[k] * v.y;
        }
        const float* dsth = inb + (cur ^ 1) * (KIN * 8) + (DD + gh) * 8 + 2 * pd;
        ull hv = pk2(acc0, acc1);
        #pragma unroll
        for (int r8 = 0; r8 < CSZ; r8++) st_remote64(dsth, r8, hv);
    }
    CLUSTER_SYNC();
    cur ^= 1;
    c0 = 0.0f; c1 = 0.0f;

    // =============== decoder (autoregressive) ===============
    const int pb = tid & 7;          // batch for pred partials
    const int dbase = tid >> 3;      // 0..31
    #pragma unroll 1
    for (int t = 0; t < TT; t++) {
        GATE_STEP(bgd);
        if (kh == 0) *(float2*)(hloc + hid * 8 + b0) = make_float2(h0v, h1v);
        __syncthreads();             // hloc ready (CTA-local)
        // pred partials over this CTA's 32 hidden units
        {
            float pa0 = 0.f, pa1 = 0.f, pa2 = 0.f;
            const bool has3 = dbase < (DD - 64);
            #pragma unroll 8
            for (int k = 0; k < 32; k++) {
                float hv = hloc[k * 8 + pb];
                pa0 += hv * wout_s[k * DD + dbase];
                pa1 += hv * wout_s[k * DD + dbase + 32];
                if (has3) pa2 += hv * wout_s[k * DD + dbase + 64];
            }
            st_remote32(ppart + RANK * DD + dbase, pb, pa0);
            st_remote32(ppart + RANK * DD + dbase + 32, pb, pa1);
            if (has3) st_remote32(ppart + RANK * DD + dbase + 64, pb, pa2);
        }
        CLUSTER_SYNC();              // h exchange + partials visible
        // owner (batch = RANK): reduce partials, sigmoid, emit + feedback
        if (tid < DD) {
            float s = bout_s[tid];
            #pragma unroll
            for (int src = 0; src < CSZ; src++) s += ppart[src * DD + tid];
            float pr = sigf(s);
            out[(((size_t)(CLUST * 8 + RANK)) * TT + t) * DD + tid] = pr;
            const float* dstx = inb + (cur ^ 1) * (KIN * 8) + tid * 8 + RANK;
            #pragma unroll
            for (int r8 = 0; r8 < CSZ; r8++) st_remote32(dstx, r8, pr);
        }
        CLUSTER_SYNC();              // pred feedback visible
        cur ^= 1;
    }
#undef GATE_STEP
}

// ---------------------------------------------------------------------------
extern "C" void kernel_launch(void* const* d_in, const int* in_sizes, int n_in,
                              void* d_out, int out_size) {
    const float* x         = (const float*)d_in[0];
    const float* Wih_e     = (const float*)d_in[1];
    const float* Whh_e     = (const float*)d_in[2];
    const float* bih_e     = (const float*)d_in[3];
    const float* bhh_e     = (const float*)d_in[4];
    const float* Wih_d     = (const float*)d_in[5];
    const float* Whh_d     = (const float*)d_in[6];
    const float* bih_d     = (const float*)d_in[7];
    const float* bhh_d     = (const float*)d_in[8];
    const float* W_lat     = (const float*)d_in[9];
    const float* b_lat     = (const float*)d_in[10];
    const float* W_decinit = (const float*)d_in[11];
    const float* b_decinit = (const float*)d_in[12];
    const float* W_out     = (const float*)d_in[13];
    const float* b_out     = (const float*)d_in[14];
    float* out = (float*)d_out;

    cudaFuncSetAttribute(lstm_cluster_kernel,
                         cudaFuncAttributeMaxDynamicSharedMemorySize, SMEM_BYTES);

    lstm_init_kernel<<<TT, 128>>>(x);
    lstm_cluster_kernel<<<NCTA, NTH, SMEM_BYTES>>>(
        Wih_e, Whh_e, bih_e, bhh_e,
        Wih_d, Whh_d, bih_d, bhh_d,
        W_lat, b_lat, W_decinit, b_decinit, W_out, b_out, out);
}